// round 16
// baseline (speedup 1.0000x reference)
#include <cuda_runtime.h>
#include <cuda_fp16.h>
#include <cstdint>

static const int NMAX = 20000;
static const int EMAX = 640000;

// Scratch (device globals: no allocation allowed)
__device__ __align__(16) __half g_msg_srch[NMAX * 128];   // fp16 node messages
__device__ __align__(16) __half g_msg_tgth[NMAX * 128];
__device__ __align__(16) float g_skip[NMAX * 128];
__device__ __align__(16) float g_acc[NMAX * 128];
__device__ float g_den[NMAX];
__device__ int g_cnt[NMAX];    // histogram
__device__ int g_off[NMAX];    // exclusive offsets (scatter cursor)
__device__ int g_srcp[EMAX];   // permuted src index
__device__ int g_tgtp[EMAX];   // permuted tgt index (sorted)

__global__ void zero_kernel(int n) {
    float4 z = make_float4(0.f, 0.f, 0.f, 0.f);
    int stride = gridDim.x * blockDim.x;
    int tid0 = blockIdx.x * blockDim.x + threadIdx.x;
    for (int i = tid0; i < n * 32; i += stride)
        reinterpret_cast<float4*>(g_acc)[i] = z;
    for (int i = tid0; i < n; i += stride) {
        g_den[i] = 0.f;
        g_cnt[i] = 0;
    }
}

// ---- counting sort by target ----
__global__ void hist_kernel(const int* __restrict__ ei, int E, int N) {
    int stride = gridDim.x * blockDim.x;
    for (int e = blockIdx.x * blockDim.x + threadIdx.x; e < E; e += stride) {
        int i = ei[E + e];
        i = (i < 0) ? 0 : (i >= N ? N - 1 : i);
        atomicAdd(&g_cnt[i], 1);
    }
}

__global__ void __launch_bounds__(1024) scan_kernel(int n) {
    __shared__ int warpsum[32];
    __shared__ int carry;
    int tid = threadIdx.x, lane = tid & 31, wid = tid >> 5;
    if (tid == 0) carry = 0;
    __syncthreads();
    for (int base = 0; base < n; base += 1024) {
        int v = (base + tid < n) ? g_cnt[base + tid] : 0;
        int s = v;
#pragma unroll
        for (int off = 1; off < 32; off <<= 1) {
            int t = __shfl_up_sync(0xffffffffu, s, off);
            if (lane >= off) s += t;
        }
        if (lane == 31) warpsum[wid] = s;
        __syncthreads();
        if (wid == 0) {
            int ws = warpsum[lane];
#pragma unroll
            for (int off = 1; off < 32; off <<= 1) {
                int t = __shfl_up_sync(0xffffffffu, ws, off);
                if (lane >= off) ws += t;
            }
            warpsum[lane] = ws;
        }
        __syncthreads();
        int excl = s - v + (wid > 0 ? warpsum[wid - 1] : 0) + carry;
        if (base + tid < n) g_off[base + tid] = excl;
        __syncthreads();
        if (tid == 0) carry += warpsum[31];
        __syncthreads();
    }
}

__global__ void scatter_kernel(const int* __restrict__ ei, int E, int N) {
    int stride = gridDim.x * blockDim.x;
    for (int e = blockIdx.x * blockDim.x + threadIdx.x; e < E; e += stride) {
        int j = ei[e], i = ei[E + e];
        j = (j < 0) ? 0 : (j >= N ? N - 1 : j);
        i = (i < 0) ? 0 : (i >= N ? N - 1 : i);
        int pos = atomicAdd(&g_off[i], 1);
        g_srcp[pos] = j;
        g_tgtp[pos] = i;
    }
}

// ---------------- helpers ----------------
__device__ __forceinline__ float prelu_f(float v, float a) {
    return v >= 0.f ? v : a * v;
}

__device__ __forceinline__ void mma_f16(float* d,
                                        uint32_t a0, uint32_t a1, uint32_t a2, uint32_t a3,
                                        uint32_t b0, uint32_t b1) {
    float c0 = d[0], c1 = d[1], c2 = d[2], c3 = d[3];
    asm volatile(
        "mma.sync.aligned.m16n8k16.row.col.f32.f16.f16.f32 "
        "{%0,%1,%2,%3}, {%4,%5,%6,%7}, {%8,%9}, {%10,%11,%12,%13};\n"
        : "=f"(d[0]), "=f"(d[1]), "=f"(d[2]), "=f"(d[3])
        : "r"(a0), "r"(a1), "r"(a2), "r"(a3), "r"(b0), "r"(b1),
          "f"(c0), "f"(c1), "f"(c2), "f"(c3));
}

__device__ __forceinline__ uint32_t pack_half2(float lo, float hi) {
    __half2 h = __floats2half2_rn(lo, hi);
    return *reinterpret_cast<uint32_t*>(&h);
}

__device__ __forceinline__ float2 h2_to_f2(uint32_t u) {
    __half2 h = *reinterpret_cast<__half2*>(&u);
    return __half22float2(h);
}

// ---------------- node GEMM via fp16 MMA ----------------
// smem: sWh 17408 halfs (34816B) | sXh 8704 halfs (17408B) | sbias 128 f (512B)
static const int NODE_SMEM_BYTES = 17408 * 2 + 8704 * 2 + 128 * 4;

__global__ void __launch_bounds__(256, 2) node3_kernel(
    const float* __restrict__ x,
    const float* __restrict__ W_src, const float* __restrict__ b_src,
    const float* __restrict__ W_tgt, const float* __restrict__ W_skip,
    int N)
{
    extern __shared__ char smraw[];
    __half* sWh = reinterpret_cast<__half*>(smraw);        // [n=128][k stride 136]
    __half* sXh = sWh + 17408;                             // [r=64][k stride 136]
    float*  sbias = reinterpret_cast<float*>(sXh + 8704);

    int tid = threadIdx.x;
    int w    = tid >> 5;
    int lane = tid & 31;
    int g    = lane >> 2;
    int tig  = lane & 3;
    int m0   = (w & 1) * 32;
    int cg   = w >> 1;
    int nbase = cg * 32;
    int n0 = blockIdx.x * 64;

    // x tile -> fp16 once
    for (int idx = tid; idx < 64 * 32; idx += 256) {
        int r = idx >> 5, c = (idx & 31) * 4;
        uint2 packed = make_uint2(0u, 0u);
        if (n0 + r < N) {
            float4 v = *reinterpret_cast<const float4*>(&x[(n0 + r) * 128 + c]);
            packed.x = pack_half2(v.x, v.y);
            packed.y = pack_half2(v.z, v.w);
        }
        *reinterpret_cast<uint2*>(&sXh[r * 136 + c]) = packed;
    }
    if (tid < 128) sbias[tid] = b_src[tid];

#pragma unroll 1
    for (int which = 0; which < 3; which++) {
        const float* W = (which == 0) ? W_src : ((which == 1) ? W_tgt : W_skip);
        __syncthreads();   // sWh reuse (and sXh/sbias ready on first iter)
        for (int idx = tid; idx < 16384; idx += 256) {
            int k = idx >> 7, n = idx & 127;
            sWh[n * 136 + k] = __float2half(W[idx]);
        }
        __syncthreads();

        float acc[2][4][4];
#pragma unroll
        for (int mb = 0; mb < 2; mb++)
#pragma unroll
            for (int nt = 0; nt < 4; nt++)
#pragma unroll
                for (int c = 0; c < 4; c++) acc[mb][nt][c] = 0.f;

#pragma unroll 4
        for (int k0 = 0; k0 < 128; k0 += 16) {
            uint32_t A[2][4];
#pragma unroll
            for (int mb = 0; mb < 2; mb++) {
                int br = m0 + mb * 16;
                A[mb][0] = *reinterpret_cast<uint32_t*>(&sXh[(br + g) * 136 + k0 + 2 * tig]);
                A[mb][1] = *reinterpret_cast<uint32_t*>(&sXh[(br + g + 8) * 136 + k0 + 2 * tig]);
                A[mb][2] = *reinterpret_cast<uint32_t*>(&sXh[(br + g) * 136 + k0 + 2 * tig + 8]);
                A[mb][3] = *reinterpret_cast<uint32_t*>(&sXh[(br + g + 8) * 136 + k0 + 2 * tig + 8]);
            }
#pragma unroll
            for (int nt = 0; nt < 4; nt++) {
                int nn = nbase + nt * 8;
                uint32_t B0 = *reinterpret_cast<uint32_t*>(&sWh[(nn + g) * 136 + k0 + 2 * tig]);
                uint32_t B1 = *reinterpret_cast<uint32_t*>(&sWh[(nn + g) * 136 + k0 + 2 * tig + 8]);
#pragma unroll
                for (int mb = 0; mb < 2; mb++)
                    mma_f16(acc[mb][nt], A[mb][0], A[mb][1], A[mb][2], A[mb][3], B0, B1);
            }
        }

#pragma unroll
        for (int mb = 0; mb < 2; mb++) {
            int br = m0 + mb * 16;
#pragma unroll
            for (int nt = 0; nt < 4; nt++) {
                int c0 = nbase + nt * 8 + 2 * tig;
                float bb0 = (which == 0) ? sbias[c0] : 0.f;
                float bb1 = (which == 0) ? sbias[c0 + 1] : 0.f;
                int r0 = n0 + br + g;
                int r1 = n0 + br + g + 8;
                if (which == 2) {
                    // skip connection stays fp32
                    if (r0 < N) {
                        float2 v = make_float2(acc[mb][nt][0], acc[mb][nt][1]);
                        *reinterpret_cast<float2*>(&g_skip[r0 * 128 + c0]) = v;
                    }
                    if (r1 < N) {
                        float2 v = make_float2(acc[mb][nt][2], acc[mb][nt][3]);
                        *reinterpret_cast<float2*>(&g_skip[r1 * 128 + c0]) = v;
                    }
                } else {
                    __half* outh = (which == 0) ? g_msg_srch : g_msg_tgth;
                    if (r0 < N)
                        *reinterpret_cast<uint32_t*>(&outh[r0 * 128 + c0]) =
                            pack_half2(acc[mb][nt][0] + bb0, acc[mb][nt][1] + bb1);
                    if (r1 < N)
                        *reinterpret_cast<uint32_t*>(&outh[r1 * 128 + c0]) =
                            pack_half2(acc[mb][nt][2] + bb0, acc[mb][nt][3] + bb1);
                }
            }
        }
    }
}

// ---------------- edge kernel (fp16 MMA, fp16 gather, seg-reduce) ------------
static const int EDGE_SMEM_BYTES = (17408 * 2 + 8704 * 2) * 2 + 704 * 4 + 128 * 4;

__global__ void __launch_bounds__(256, 2) edge_kernel(
    const float* __restrict__ W1, const float* __restrict__ b1,
    const float* __restrict__ W2, const float* __restrict__ b2,
    const float* __restrict__ Wg,
    const float* __restrict__ a0p, const float* __restrict__ a1p,
    int E, int N)
{
    extern __shared__ char smraw[];
    __half* sW1h = reinterpret_cast<__half*>(smraw);
    __half* sW2h = sW1h + 17408;
    __half* sH0h = sW2h + 17408;
    __half* sH1h = sH0h + 8704;
    float*  sMsg = reinterpret_cast<float*>(sH0h);   // overlays sH0h+sH1h
    float*  sb1  = reinterpret_cast<float*>(sH1h + 8704);
    float*  sb2  = sb1 + 128;
    float*  sWg  = sb2 + 128;
    float*  sGP  = sWg + 128;    // [4][64]
    float*  sEx  = sGP + 256;    // [64]
    int*    sJ   = reinterpret_cast<int*>(sEx + 64);
    int*    sI   = sJ + 64;

    int tid = threadIdx.x;
    int w    = tid >> 5;
    int lane = tid & 31;
    int g    = lane >> 2;
    int tig  = lane & 3;
    int m0   = (w & 1) * 32;
    int cg   = w >> 1;
    int nbase = cg * 32;

    float a0 = *a0p, a1 = *a1p;

    for (int idx = tid; idx < 16384; idx += 256) {
        int k = idx >> 7, n = idx & 127;
        sW1h[n * 136 + k] = __float2half(W1[idx]);
        sW2h[n * 136 + k] = __float2half(W2[idx]);
    }
    if (tid < 128) { sb1[tid] = b1[tid]; sb2[tid] = b2[tid]; sWg[tid] = Wg[tid]; }
    __syncthreads();

    int nTiles = (E + 63) >> 6;

    for (int tile = blockIdx.x; tile < nTiles; tile += gridDim.x) {
        int e0 = tile << 6;
        if (tid < 64) {
            int e = e0 + tid;
            sJ[tid] = (e < E) ? g_srcp[e] : 0;
            sI[tid] = (e < E) ? g_tgtp[e] : 0;
        }
        __syncthreads();

        // gather (fp16 source): h0 = fp16(prelu(msg_src[j] + msg_tgt[i], a0))
#pragma unroll
        for (int it = 0; it < 8; it++) {
            int idx = tid + it * 256;
            int e = idx >> 5, c = (idx & 31) * 4;
            uint2 packed = make_uint2(0u, 0u);
            if (e0 + e < E) {
                uint2 sv = *reinterpret_cast<const uint2*>(&g_msg_srch[sJ[e] * 128 + c]);
                uint2 tv = *reinterpret_cast<const uint2*>(&g_msg_tgth[sI[e] * 128 + c]);
                float2 s01 = h2_to_f2(sv.x), s23 = h2_to_f2(sv.y);
                float2 t01 = h2_to_f2(tv.x), t23 = h2_to_f2(tv.y);
                packed.x = pack_half2(prelu_f(s01.x + t01.x, a0), prelu_f(s01.y + t01.y, a0));
                packed.y = pack_half2(prelu_f(s23.x + t23.x, a0), prelu_f(s23.y + t23.y, a0));
            }
            *reinterpret_cast<uint2*>(&sH0h[e * 136 + c]) = packed;
        }
        __syncthreads();

        // ---- GEMM1 ----
        float acc[2][4][4];
#pragma unroll
        for (int mb = 0; mb < 2; mb++)
#pragma unroll
            for (int nt = 0; nt < 4; nt++)
#pragma unroll
                for (int c = 0; c < 4; c++) acc[mb][nt][c] = 0.f;

#pragma unroll 4
        for (int k0 = 0; k0 < 128; k0 += 16) {
            uint32_t A[2][4];
#pragma unroll
            for (int mb = 0; mb < 2; mb++) {
                int br = m0 + mb * 16;
                A[mb][0] = *reinterpret_cast<uint32_t*>(&sH0h[(br + g) * 136 + k0 + 2 * tig]);
                A[mb][1] = *reinterpret_cast<uint32_t*>(&sH0h[(br + g + 8) * 136 + k0 + 2 * tig]);
                A[mb][2] = *reinterpret_cast<uint32_t*>(&sH0h[(br + g) * 136 + k0 + 2 * tig + 8]);
                A[mb][3] = *reinterpret_cast<uint32_t*>(&sH0h[(br + g + 8) * 136 + k0 + 2 * tig + 8]);
            }
#pragma unroll
            for (int nt = 0; nt < 4; nt++) {
                int n0 = nbase + nt * 8;
                uint32_t B0 = *reinterpret_cast<uint32_t*>(&sW1h[(n0 + g) * 136 + k0 + 2 * tig]);
                uint32_t B1 = *reinterpret_cast<uint32_t*>(&sW1h[(n0 + g) * 136 + k0 + 2 * tig + 8]);
#pragma unroll
                for (int mb = 0; mb < 2; mb++)
                    mma_f16(acc[mb][nt], A[mb][0], A[mb][1], A[mb][2], A[mb][3], B0, B1);
            }
        }

        // epilogue 1: bias + prelu -> fp16 sH1
#pragma unroll
        for (int mb = 0; mb < 2; mb++) {
            int br = m0 + mb * 16;
#pragma unroll
            for (int nt = 0; nt < 4; nt++) {
                int c0 = nbase + nt * 8 + 2 * tig;
                *reinterpret_cast<uint32_t*>(&sH1h[(br + g) * 136 + c0]) =
                    pack_half2(prelu_f(acc[mb][nt][0] + sb1[c0], a1),
                               prelu_f(acc[mb][nt][1] + sb1[c0 + 1], a1));
                *reinterpret_cast<uint32_t*>(&sH1h[(br + g + 8) * 136 + c0]) =
                    pack_half2(prelu_f(acc[mb][nt][2] + sb1[c0], a1),
                               prelu_f(acc[mb][nt][3] + sb1[c0 + 1], a1));
            }
        }
        __syncthreads();

        // ---- GEMM2 ----
        float acc2[2][4][4];
#pragma unroll
        for (int mb = 0; mb < 2; mb++)
#pragma unroll
            for (int nt = 0; nt < 4; nt++)
#pragma unroll
                for (int c = 0; c < 4; c++) acc2[mb][nt][c] = 0.f;

#pragma unroll 4
        for (int k0 = 0; k0 < 128; k0 += 16) {
            uint32_t A[2][4];
#pragma unroll
            for (int mb = 0; mb < 2; mb++) {
                int br = m0 + mb * 16;
                A[mb][0] = *reinterpret_cast<uint32_t*>(&sH1h[(br + g) * 136 + k0 + 2 * tig]);
                A[mb][1] = *reinterpret_cast<uint32_t*>(&sH1h[(br + g + 8) * 136 + k0 + 2 * tig]);
                A[mb][2] = *reinterpret_cast<uint32_t*>(&sH1h[(br + g) * 136 + k0 + 2 * tig + 8]);
                A[mb][3] = *reinterpret_cast<uint32_t*>(&sH1h[(br + g + 8) * 136 + k0 + 2 * tig + 8]);
            }
#pragma unroll
            for (int nt = 0; nt < 4; nt++) {
                int n0 = nbase + nt * 8;
                uint32_t B0 = *reinterpret_cast<uint32_t*>(&sW2h[(n0 + g) * 136 + k0 + 2 * tig]);
                uint32_t B1 = *reinterpret_cast<uint32_t*>(&sW2h[(n0 + g) * 136 + k0 + 2 * tig + 8]);
#pragma unroll
                for (int mb = 0; mb < 2; mb++)
                    mma_f16(acc2[mb][nt], A[mb][0], A[mb][1], A[mb][2], A[mb][3], B0, B1);
            }
        }

        // add b2; gate partials over this warp's 32 cols
        float p[2][2] = {{0.f, 0.f}, {0.f, 0.f}};
#pragma unroll
        for (int mb = 0; mb < 2; mb++)
#pragma unroll
            for (int nt = 0; nt < 4; nt++) {
                int c0 = nbase + nt * 8 + 2 * tig;
                acc2[mb][nt][0] += sb2[c0];
                acc2[mb][nt][1] += sb2[c0 + 1];
                acc2[mb][nt][2] += sb2[c0];
                acc2[mb][nt][3] += sb2[c0 + 1];
                p[mb][0] = fmaf(acc2[mb][nt][0], sWg[c0], p[mb][0]);
                p[mb][0] = fmaf(acc2[mb][nt][1], sWg[c0 + 1], p[mb][0]);
                p[mb][1] = fmaf(acc2[mb][nt][2], sWg[c0], p[mb][1]);
                p[mb][1] = fmaf(acc2[mb][nt][3], sWg[c0 + 1], p[mb][1]);
            }
#pragma unroll
        for (int mb = 0; mb < 2; mb++) {
#pragma unroll
            for (int half = 0; half < 2; half++) {
                p[mb][half] += __shfl_xor_sync(0xffffffffu, p[mb][half], 1);
                p[mb][half] += __shfl_xor_sync(0xffffffffu, p[mb][half], 2);
            }
        }
        if (tig == 0) {
#pragma unroll
            for (int mb = 0; mb < 2; mb++) {
                sGP[cg * 64 + m0 + mb * 16 + g] = p[mb][0];
                sGP[cg * 64 + m0 + mb * 16 + 8 + g] = p[mb][1];
            }
        }
        __syncthreads();

        // stage msg (fp32, with b2) into sMsg; compute sEx per row
#pragma unroll
        for (int mb = 0; mb < 2; mb++) {
            int br = m0 + mb * 16;
#pragma unroll
            for (int nt = 0; nt < 4; nt++) {
                int c0 = nbase + nt * 8 + 2 * tig;
                sMsg[(br + g) * 130 + c0]     = acc2[mb][nt][0];
                sMsg[(br + g) * 130 + c0 + 1] = acc2[mb][nt][1];
                sMsg[(br + g + 8) * 130 + c0]     = acc2[mb][nt][2];
                sMsg[(br + g + 8) * 130 + c0 + 1] = acc2[mb][nt][3];
            }
        }
        if (tid < 64) {
            float gate = sGP[tid] + sGP[64 + tid] + sGP[128 + tid] + sGP[192 + tid];
            sEx[tid] = (e0 + tid < E) ? __expf(gate) : 0.f;
        }
        __syncthreads();

        // segmented reduction over sorted targets: 2 threads per column
        {
            int c = tid & 127;
            int half = tid >> 7;
            int r0 = half * 32;
            float sum = 0.f, dsum = 0.f;
            int cur = sI[r0];
#pragma unroll 8
            for (int rr = 0; rr < 32; rr++) {
                int r = r0 + rr;
                float ex = sEx[r];
                sum = fmaf(ex, sMsg[r * 130 + c], sum);
                if (c == 0) dsum += ex;
                int nxt = (rr == 31) ? -1 : sI[r + 1];
                if (nxt != cur) {
                    atomicAdd(&g_acc[cur * 128 + c], sum);
                    if (c == 0) atomicAdd(&g_den[cur], dsum);
                    sum = 0.f; dsum = 0.f; cur = nxt;
                }
            }
        }
        __syncthreads();  // protect smem before next tile
    }
}

// ---------------- final per-node kernel ----------------
__global__ void __launch_bounds__(256) final_kernel(
    const float* __restrict__ gamma, const float* __restrict__ beta,
    float* __restrict__ out, int N)
{
    int node = (blockIdx.x * blockDim.x + threadIdx.x) >> 5;
    int lane = threadIdx.x & 31;
    if (node >= N) return;

    float4 a = *reinterpret_cast<const float4*>(&g_acc[node * 128 + lane * 4]);
    float4 s = *reinterpret_cast<const float4*>(&g_skip[node * 128 + lane * 4]);
    float dn = g_den[node];
    float inv = dn > 0.f ? 1.f / dn : 0.f;

    float v0 = fmaf(a.x, inv, s.x);
    float v1 = fmaf(a.y, inv, s.y);
    float v2 = fmaf(a.z, inv, s.z);
    float v3 = fmaf(a.w, inv, s.w);

    float sum = v0 + v1 + v2 + v3;
#pragma unroll
    for (int off = 16; off; off >>= 1) sum += __shfl_xor_sync(0xffffffffu, sum, off);
    float mu = sum * (1.f / 128.f);

    float d0 = v0 - mu, d1 = v1 - mu, d2 = v2 - mu, d3 = v3 - mu;
    float sq = d0 * d0 + d1 * d1 + d2 * d2 + d3 * d3;
#pragma unroll
    for (int off = 16; off; off >>= 1) sq += __shfl_xor_sync(0xffffffffu, sq, off);
    float rs = rsqrtf(sq * (1.f / 128.f) + 1e-5f);

    float4 gm = *reinterpret_cast<const float4*>(&gamma[lane * 4]);
    float4 bt = *reinterpret_cast<const float4*>(&beta[lane * 4]);
    float4 o;
    o.x = fmaf(d0 * rs, gm.x, bt.x);
    o.y = fmaf(d1 * rs, gm.y, bt.y);
    o.z = fmaf(d2 * rs, gm.z, bt.z);
    o.w = fmaf(d3 * rs, gm.w, bt.w);
    *reinterpret_cast<float4*>(&out[node * 128 + lane * 4]) = o;
}

extern "C" void kernel_launch(void* const* d_in, const int* in_sizes, int n_in,
                              void* d_out, int out_size)
{
    const float* x      = (const float*)d_in[0];
    const int*   ei     = (const int*)d_in[1];
    const float* W_src  = (const float*)d_in[2];
    const float* b_src  = (const float*)d_in[3];
    const float* W_tgt  = (const float*)d_in[4];
    const float* W_skip = (const float*)d_in[5];
    const float* a0     = (const float*)d_in[6];
    const float* W1     = (const float*)d_in[7];
    const float* b1     = (const float*)d_in[8];
    const float* a1     = (const float*)d_in[9];
    const float* W2     = (const float*)d_in[10];
    const float* b2     = (const float*)d_in[11];
    const float* Wg     = (const float*)d_in[12];
    const float* gamma  = (const float*)d_in[13];
    const float* beta   = (const float*)d_in[14];
    float* out = (float*)d_out;

    int N = in_sizes[0] / 128;
    int E = in_sizes[1] / 2;
    if (E > EMAX) E = EMAX;

    static int sms = 0;
    if (sms == 0) {
        cudaFuncSetAttribute(node3_kernel, cudaFuncAttributeMaxDynamicSharedMemorySize, NODE_SMEM_BYTES);
        cudaFuncSetAttribute(edge_kernel, cudaFuncAttributeMaxDynamicSharedMemorySize, EDGE_SMEM_BYTES);
        int dev = 0, v = 148;
        cudaGetDevice(&dev);
        cudaDeviceGetAttribute(&v, cudaDevAttrMultiProcessorCount, dev);
        sms = (v > 0) ? v : 148;
    }

    zero_kernel<<<256, 256>>>(N);
    hist_kernel<<<(E + 255) / 256, 256>>>(ei, E, N);
    scan_kernel<<<1, 1024>>>(N);
    scatter_kernel<<<(E + 255) / 256, 256>>>(ei, E, N);
    int nb = (N + 63) / 64;
    node3_kernel<<<nb, 256, NODE_SMEM_BYTES>>>(x, W_src, b_src, W_tgt, W_skip, N);
    edge_kernel<<<sms * 2, 256, EDGE_SMEM_BYTES>>>(W1, b1, W2, b2, Wg, a0, a1, E, N);
    final_kernel<<<(N * 32 + 255) / 256, 256>>>(gamma, beta, out, N);
}

// round 17
// speedup vs baseline: 1.5912x; 1.5912x over previous
#include <cuda_runtime.h>
#include <cuda_fp16.h>
#include <cstdint>

static const int NMAX = 20000;
static const int EMAX = 640000;

// Scratch (device globals: no allocation allowed)
__device__ __align__(16) __half g_msg_srch[NMAX * 128];   // fp16 node messages
__device__ __align__(16) __half g_msg_tgth[NMAX * 128];
__device__ __align__(16) float g_skip[NMAX * 128];
__device__ __align__(16) float g_acc[NMAX * 128];
__device__ float g_den[NMAX];
__device__ int g_cnt[NMAX];    // histogram
__device__ int g_off[NMAX];    // exclusive offsets (scatter cursor)
__device__ int g_srcp[EMAX];   // permuted src index
__device__ int g_tgtp[EMAX];   // permuted tgt index (sorted)

__global__ void zero_kernel(int n) {
    float4 z = make_float4(0.f, 0.f, 0.f, 0.f);
    int stride = gridDim.x * blockDim.x;
    int tid0 = blockIdx.x * blockDim.x + threadIdx.x;
    for (int i = tid0; i < n * 32; i += stride)
        reinterpret_cast<float4*>(g_acc)[i] = z;
    for (int i = tid0; i < n; i += stride) {
        g_den[i] = 0.f;
        g_cnt[i] = 0;
    }
}

// ---- counting sort by target ----
__global__ void hist_kernel(const int* __restrict__ ei, int E, int N) {
    int stride = gridDim.x * blockDim.x;
    for (int e = blockIdx.x * blockDim.x + threadIdx.x; e < E; e += stride) {
        int i = ei[E + e];
        i = (i < 0) ? 0 : (i >= N ? N - 1 : i);
        atomicAdd(&g_cnt[i], 1);
    }
}

__global__ void __launch_bounds__(1024) scan_kernel(int n) {
    __shared__ int warpsum[32];
    __shared__ int carry;
    int tid = threadIdx.x, lane = tid & 31, wid = tid >> 5;
    if (tid == 0) carry = 0;
    __syncthreads();
    for (int base = 0; base < n; base += 1024) {
        int v = (base + tid < n) ? g_cnt[base + tid] : 0;
        int s = v;
#pragma unroll
        for (int off = 1; off < 32; off <<= 1) {
            int t = __shfl_up_sync(0xffffffffu, s, off);
            if (lane >= off) s += t;
        }
        if (lane == 31) warpsum[wid] = s;
        __syncthreads();
        if (wid == 0) {
            int ws = warpsum[lane];
#pragma unroll
            for (int off = 1; off < 32; off <<= 1) {
                int t = __shfl_up_sync(0xffffffffu, ws, off);
                if (lane >= off) ws += t;
            }
            warpsum[lane] = ws;
        }
        __syncthreads();
        int excl = s - v + (wid > 0 ? warpsum[wid - 1] : 0) + carry;
        if (base + tid < n) g_off[base + tid] = excl;
        __syncthreads();
        if (tid == 0) carry += warpsum[31];
        __syncthreads();
    }
}

__global__ void scatter_kernel(const int* __restrict__ ei, int E, int N) {
    int stride = gridDim.x * blockDim.x;
    for (int e = blockIdx.x * blockDim.x + threadIdx.x; e < E; e += stride) {
        int j = ei[e], i = ei[E + e];
        j = (j < 0) ? 0 : (j >= N ? N - 1 : j);
        i = (i < 0) ? 0 : (i >= N ? N - 1 : i);
        int pos = atomicAdd(&g_off[i], 1);
        g_srcp[pos] = j;
        g_tgtp[pos] = i;
    }
}

// ---------------- helpers ----------------
__device__ __forceinline__ float prelu_f(float v, float a) {
    return v >= 0.f ? v : a * v;
}

__device__ __forceinline__ void mma_f16(float* d,
                                        uint32_t a0, uint32_t a1, uint32_t a2, uint32_t a3,
                                        uint32_t b0, uint32_t b1) {
    float c0 = d[0], c1 = d[1], c2 = d[2], c3 = d[3];
    asm volatile(
        "mma.sync.aligned.m16n8k16.row.col.f32.f16.f16.f32 "
        "{%0,%1,%2,%3}, {%4,%5,%6,%7}, {%8,%9}, {%10,%11,%12,%13};\n"
        : "=f"(d[0]), "=f"(d[1]), "=f"(d[2]), "=f"(d[3])
        : "r"(a0), "r"(a1), "r"(a2), "r"(a3), "r"(b0), "r"(b1),
          "f"(c0), "f"(c1), "f"(c2), "f"(c3));
}

__device__ __forceinline__ uint32_t pack_half2(float lo, float hi) {
    __half2 h = __floats2half2_rn(lo, hi);
    return *reinterpret_cast<uint32_t*>(&h);
}

__device__ __forceinline__ float2 h2_to_f2(uint32_t u) {
    __half2 h = *reinterpret_cast<__half2*>(&u);
    return __half22float2(h);
}

// add two packed half2 vectors, apply prelu, in fp32 then repack
__device__ __forceinline__ uint32_t add_prelu_pack(uint32_t a, uint32_t b, float al) {
    float2 fa = h2_to_f2(a), fb = h2_to_f2(b);
    return pack_half2(prelu_f(fa.x + fb.x, al), prelu_f(fa.y + fb.y, al));
}

// ---------------- node GEMM via fp16 MMA ----------------
// smem: sWh 17408 halfs (34816B) | sXh 8704 halfs (17408B) | sbias 128 f (512B)
static const int NODE_SMEM_BYTES = 17408 * 2 + 8704 * 2 + 128 * 4;

__global__ void __launch_bounds__(256, 2) node3_kernel(
    const float* __restrict__ x,
    const float* __restrict__ W_src, const float* __restrict__ b_src,
    const float* __restrict__ W_tgt, const float* __restrict__ W_skip,
    int N)
{
    extern __shared__ char smraw[];
    __half* sWh = reinterpret_cast<__half*>(smraw);        // [n=128][k stride 136]
    __half* sXh = sWh + 17408;                             // [r=64][k stride 136]
    float*  sbias = reinterpret_cast<float*>(sXh + 8704);

    int tid = threadIdx.x;
    int w    = tid >> 5;
    int lane = tid & 31;
    int g    = lane >> 2;
    int tig  = lane & 3;
    int m0   = (w & 1) * 32;
    int cg   = w >> 1;
    int nbase = cg * 32;
    int n0 = blockIdx.x * 64;

    // x tile -> fp16 once
    for (int idx = tid; idx < 64 * 32; idx += 256) {
        int r = idx >> 5, c = (idx & 31) * 4;
        uint2 packed = make_uint2(0u, 0u);
        if (n0 + r < N) {
            float4 v = *reinterpret_cast<const float4*>(&x[(n0 + r) * 128 + c]);
            packed.x = pack_half2(v.x, v.y);
            packed.y = pack_half2(v.z, v.w);
        }
        *reinterpret_cast<uint2*>(&sXh[r * 136 + c]) = packed;
    }
    if (tid < 128) sbias[tid] = b_src[tid];

#pragma unroll 1
    for (int which = 0; which < 3; which++) {
        const float* W = (which == 0) ? W_src : ((which == 1) ? W_tgt : W_skip);
        __syncthreads();   // sWh reuse (and sXh/sbias ready on first iter)
        for (int idx = tid; idx < 16384; idx += 256) {
            int k = idx >> 7, n = idx & 127;
            sWh[n * 136 + k] = __float2half(W[idx]);
        }
        __syncthreads();

        float acc[2][4][4];
#pragma unroll
        for (int mb = 0; mb < 2; mb++)
#pragma unroll
            for (int nt = 0; nt < 4; nt++)
#pragma unroll
                for (int c = 0; c < 4; c++) acc[mb][nt][c] = 0.f;

#pragma unroll 4
        for (int k0 = 0; k0 < 128; k0 += 16) {
            uint32_t A[2][4];
#pragma unroll
            for (int mb = 0; mb < 2; mb++) {
                int br = m0 + mb * 16;
                A[mb][0] = *reinterpret_cast<uint32_t*>(&sXh[(br + g) * 136 + k0 + 2 * tig]);
                A[mb][1] = *reinterpret_cast<uint32_t*>(&sXh[(br + g + 8) * 136 + k0 + 2 * tig]);
                A[mb][2] = *reinterpret_cast<uint32_t*>(&sXh[(br + g) * 136 + k0 + 2 * tig + 8]);
                A[mb][3] = *reinterpret_cast<uint32_t*>(&sXh[(br + g + 8) * 136 + k0 + 2 * tig + 8]);
            }
#pragma unroll
            for (int nt = 0; nt < 4; nt++) {
                int nn = nbase + nt * 8;
                uint32_t B0 = *reinterpret_cast<uint32_t*>(&sWh[(nn + g) * 136 + k0 + 2 * tig]);
                uint32_t B1 = *reinterpret_cast<uint32_t*>(&sWh[(nn + g) * 136 + k0 + 2 * tig + 8]);
#pragma unroll
                for (int mb = 0; mb < 2; mb++)
                    mma_f16(acc[mb][nt], A[mb][0], A[mb][1], A[mb][2], A[mb][3], B0, B1);
            }
        }

#pragma unroll
        for (int mb = 0; mb < 2; mb++) {
            int br = m0 + mb * 16;
#pragma unroll
            for (int nt = 0; nt < 4; nt++) {
                int c0 = nbase + nt * 8 + 2 * tig;
                float bb0 = (which == 0) ? sbias[c0] : 0.f;
                float bb1 = (which == 0) ? sbias[c0 + 1] : 0.f;
                int r0 = n0 + br + g;
                int r1 = n0 + br + g + 8;
                if (which == 2) {
                    // skip connection stays fp32
                    if (r0 < N) {
                        float2 v = make_float2(acc[mb][nt][0], acc[mb][nt][1]);
                        *reinterpret_cast<float2*>(&g_skip[r0 * 128 + c0]) = v;
                    }
                    if (r1 < N) {
                        float2 v = make_float2(acc[mb][nt][2], acc[mb][nt][3]);
                        *reinterpret_cast<float2*>(&g_skip[r1 * 128 + c0]) = v;
                    }
                } else {
                    __half* outh = (which == 0) ? g_msg_srch : g_msg_tgth;
                    if (r0 < N)
                        *reinterpret_cast<uint32_t*>(&outh[r0 * 128 + c0]) =
                            pack_half2(acc[mb][nt][0] + bb0, acc[mb][nt][1] + bb1);
                    if (r1 < N)
                        *reinterpret_cast<uint32_t*>(&outh[r1 * 128 + c0]) =
                            pack_half2(acc[mb][nt][2] + bb0, acc[mb][nt][3] + bb1);
                }
            }
        }
    }
}

// ---------------- edge kernel (fp16 MMA, wide fp16 gather, seg-reduce) -------
static const int EDGE_SMEM_BYTES = (17408 * 2 + 8704 * 2) * 2 + 704 * 4 + 128 * 4;

__global__ void __launch_bounds__(256, 2) edge_kernel(
    const float* __restrict__ W1, const float* __restrict__ b1,
    const float* __restrict__ W2, const float* __restrict__ b2,
    const float* __restrict__ Wg,
    const float* __restrict__ a0p, const float* __restrict__ a1p,
    int E, int N)
{
    extern __shared__ char smraw[];
    __half* sW1h = reinterpret_cast<__half*>(smraw);
    __half* sW2h = sW1h + 17408;
    __half* sH0h = sW2h + 17408;
    __half* sH1h = sH0h + 8704;
    float*  sMsg = reinterpret_cast<float*>(sH0h);   // overlays sH0h+sH1h
    float*  sb1  = reinterpret_cast<float*>(sH1h + 8704);
    float*  sb2  = sb1 + 128;
    float*  sWg  = sb2 + 128;
    float*  sGP  = sWg + 128;    // [4][64]
    float*  sEx  = sGP + 256;    // [64]
    int*    sJ   = reinterpret_cast<int*>(sEx + 64);
    int*    sI   = sJ + 64;

    int tid = threadIdx.x;
    int w    = tid >> 5;
    int lane = tid & 31;
    int g    = lane >> 2;
    int tig  = lane & 3;
    int m0   = (w & 1) * 32;
    int cg   = w >> 1;
    int nbase = cg * 32;

    float a0 = *a0p, a1 = *a1p;

    for (int idx = tid; idx < 16384; idx += 256) {
        int k = idx >> 7, n = idx & 127;
        sW1h[n * 136 + k] = __float2half(W1[idx]);
        sW2h[n * 136 + k] = __float2half(W2[idx]);
    }
    if (tid < 128) { sb1[tid] = b1[tid]; sb2[tid] = b2[tid]; sWg[tid] = Wg[tid]; }
    __syncthreads();

    int nTiles = (E + 63) >> 6;

    for (int tile = blockIdx.x; tile < nTiles; tile += gridDim.x) {
        int e0 = tile << 6;
        if (tid < 64) {
            int e = e0 + tid;
            sJ[tid] = (e < E) ? g_srcp[e] : 0;
            sI[tid] = (e < E) ? g_tgtp[e] : 0;
        }
        __syncthreads();

        // gather (fp16, 16B loads): h0 = fp16(prelu(msg_src[j] + msg_tgt[i], a0))
        // 64 rows x 16 slots of 8 halves; 4 iterations of 256 threads
#pragma unroll
        for (int it = 0; it < 4; it++) {
            int idx = tid + it * 256;
            int e = idx >> 4, c = (idx & 15) * 8;
            uint4 packed = make_uint4(0u, 0u, 0u, 0u);
            if (e0 + e < E) {
                uint4 sv = *reinterpret_cast<const uint4*>(&g_msg_srch[sJ[e] * 128 + c]);
                uint4 tv = *reinterpret_cast<const uint4*>(&g_msg_tgth[sI[e] * 128 + c]);
                packed.x = add_prelu_pack(sv.x, tv.x, a0);
                packed.y = add_prelu_pack(sv.y, tv.y, a0);
                packed.z = add_prelu_pack(sv.z, tv.z, a0);
                packed.w = add_prelu_pack(sv.w, tv.w, a0);
            }
            *reinterpret_cast<uint4*>(&sH0h[e * 136 + c]) = packed;
        }
        __syncthreads();

        // ---- GEMM1 ----
        float acc[2][4][4];
#pragma unroll
        for (int mb = 0; mb < 2; mb++)
#pragma unroll
            for (int nt = 0; nt < 4; nt++)
#pragma unroll
                for (int c = 0; c < 4; c++) acc[mb][nt][c] = 0.f;

#pragma unroll 4
        for (int k0 = 0; k0 < 128; k0 += 16) {
            uint32_t A[2][4];
#pragma unroll
            for (int mb = 0; mb < 2; mb++) {
                int br = m0 + mb * 16;
                A[mb][0] = *reinterpret_cast<uint32_t*>(&sH0h[(br + g) * 136 + k0 + 2 * tig]);
                A[mb][1] = *reinterpret_cast<uint32_t*>(&sH0h[(br + g + 8) * 136 + k0 + 2 * tig]);
                A[mb][2] = *reinterpret_cast<uint32_t*>(&sH0h[(br + g) * 136 + k0 + 2 * tig + 8]);
                A[mb][3] = *reinterpret_cast<uint32_t*>(&sH0h[(br + g + 8) * 136 + k0 + 2 * tig + 8]);
            }
#pragma unroll
            for (int nt = 0; nt < 4; nt++) {
                int n0 = nbase + nt * 8;
                uint32_t B0 = *reinterpret_cast<uint32_t*>(&sW1h[(n0 + g) * 136 + k0 + 2 * tig]);
                uint32_t B1 = *reinterpret_cast<uint32_t*>(&sW1h[(n0 + g) * 136 + k0 + 2 * tig + 8]);
#pragma unroll
                for (int mb = 0; mb < 2; mb++)
                    mma_f16(acc[mb][nt], A[mb][0], A[mb][1], A[mb][2], A[mb][3], B0, B1);
            }
        }

        // epilogue 1: bias + prelu -> fp16 sH1
#pragma unroll
        for (int mb = 0; mb < 2; mb++) {
            int br = m0 + mb * 16;
#pragma unroll
            for (int nt = 0; nt < 4; nt++) {
                int c0 = nbase + nt * 8 + 2 * tig;
                *reinterpret_cast<uint32_t*>(&sH1h[(br + g) * 136 + c0]) =
                    pack_half2(prelu_f(acc[mb][nt][0] + sb1[c0], a1),
                               prelu_f(acc[mb][nt][1] + sb1[c0 + 1], a1));
                *reinterpret_cast<uint32_t*>(&sH1h[(br + g + 8) * 136 + c0]) =
                    pack_half2(prelu_f(acc[mb][nt][2] + sb1[c0], a1),
                               prelu_f(acc[mb][nt][3] + sb1[c0 + 1], a1));
            }
        }
        __syncthreads();

        // ---- GEMM2 ----
        float acc2[2][4][4];
#pragma unroll
        for (int mb = 0; mb < 2; mb++)
#pragma unroll
            for (int nt = 0; nt < 4; nt++)
#pragma unroll
                for (int c = 0; c < 4; c++) acc2[mb][nt][c] = 0.f;

#pragma unroll 4
        for (int k0 = 0; k0 < 128; k0 += 16) {
            uint32_t A[2][4];
#pragma unroll
            for (int mb = 0; mb < 2; mb++) {
                int br = m0 + mb * 16;
                A[mb][0] = *reinterpret_cast<uint32_t*>(&sH1h[(br + g) * 136 + k0 + 2 * tig]);
                A[mb][1] = *reinterpret_cast<uint32_t*>(&sH1h[(br + g + 8) * 136 + k0 + 2 * tig]);
                A[mb][2] = *reinterpret_cast<uint32_t*>(&sH1h[(br + g) * 136 + k0 + 2 * tig + 8]);
                A[mb][3] = *reinterpret_cast<uint32_t*>(&sH1h[(br + g + 8) * 136 + k0 + 2 * tig + 8]);
            }
#pragma unroll
            for (int nt = 0; nt < 4; nt++) {
                int n0 = nbase + nt * 8;
                uint32_t B0 = *reinterpret_cast<uint32_t*>(&sW2h[(n0 + g) * 136 + k0 + 2 * tig]);
                uint32_t B1 = *reinterpret_cast<uint32_t*>(&sW2h[(n0 + g) * 136 + k0 + 2 * tig + 8]);
#pragma unroll
                for (int mb = 0; mb < 2; mb++)
                    mma_f16(acc2[mb][nt], A[mb][0], A[mb][1], A[mb][2], A[mb][3], B0, B1);
            }
        }

        // add b2; gate partials over this warp's 32 cols
        float p[2][2] = {{0.f, 0.f}, {0.f, 0.f}};
#pragma unroll
        for (int mb = 0; mb < 2; mb++)
#pragma unroll
            for (int nt = 0; nt < 4; nt++) {
                int c0 = nbase + nt * 8 + 2 * tig;
                acc2[mb][nt][0] += sb2[c0];
                acc2[mb][nt][1] += sb2[c0 + 1];
                acc2[mb][nt][2] += sb2[c0];
                acc2[mb][nt][3] += sb2[c0 + 1];
                p[mb][0] = fmaf(acc2[mb][nt][0], sWg[c0], p[mb][0]);
                p[mb][0] = fmaf(acc2[mb][nt][1], sWg[c0 + 1], p[mb][0]);
                p[mb][1] = fmaf(acc2[mb][nt][2], sWg[c0], p[mb][1]);
                p[mb][1] = fmaf(acc2[mb][nt][3], sWg[c0 + 1], p[mb][1]);
            }
#pragma unroll
        for (int mb = 0; mb < 2; mb++) {
#pragma unroll
            for (int half = 0; half < 2; half++) {
                p[mb][half] += __shfl_xor_sync(0xffffffffu, p[mb][half], 1);
                p[mb][half] += __shfl_xor_sync(0xffffffffu, p[mb][half], 2);
            }
        }
        if (tig == 0) {
#pragma unroll
            for (int mb = 0; mb < 2; mb++) {
                sGP[cg * 64 + m0 + mb * 16 + g] = p[mb][0];
                sGP[cg * 64 + m0 + mb * 16 + 8 + g] = p[mb][1];
            }
        }
        __syncthreads();

        // stage msg (fp32, with b2) into sMsg; compute sEx per row
#pragma unroll
        for (int mb = 0; mb < 2; mb++) {
            int br = m0 + mb * 16;
#pragma unroll
            for (int nt = 0; nt < 4; nt++) {
                int c0 = nbase + nt * 8 + 2 * tig;
                sMsg[(br + g) * 130 + c0]     = acc2[mb][nt][0];
                sMsg[(br + g) * 130 + c0 + 1] = acc2[mb][nt][1];
                sMsg[(br + g + 8) * 130 + c0]     = acc2[mb][nt][2];
                sMsg[(br + g + 8) * 130 + c0 + 1] = acc2[mb][nt][3];
            }
        }
        if (tid < 64) {
            float gate = sGP[tid] + sGP[64 + tid] + sGP[128 + tid] + sGP[192 + tid];
            sEx[tid] = (e0 + tid < E) ? __expf(gate) : 0.f;
        }
        __syncthreads();

        // segmented reduction over sorted targets: 2 threads per column
        {
            int c = tid & 127;
            int half = tid >> 7;
            int r0 = half * 32;
            float sum = 0.f, dsum = 0.f;
            int cur = sI[r0];
#pragma unroll 8
            for (int rr = 0; rr < 32; rr++) {
                int r = r0 + rr;
                float ex = sEx[r];
                sum = fmaf(ex, sMsg[r * 130 + c], sum);
                if (c == 0) dsum += ex;
                int nxt = (rr == 31) ? -1 : sI[r + 1];
                if (nxt != cur) {
                    atomicAdd(&g_acc[cur * 128 + c], sum);
                    if (c == 0) atomicAdd(&g_den[cur], dsum);
                    sum = 0.f; dsum = 0.f; cur = nxt;
                }
            }
        }
        __syncthreads();  // protect smem before next tile
    }
}

// ---------------- final per-node kernel ----------------
__global__ void __launch_bounds__(256) final_kernel(
    const float* __restrict__ gamma, const float* __restrict__ beta,
    float* __restrict__ out, int N)
{
    int node = (blockIdx.x * blockDim.x + threadIdx.x) >> 5;
    int lane = threadIdx.x & 31;
    if (node >= N) return;

    float4 a = *reinterpret_cast<const float4*>(&g_acc[node * 128 + lane * 4]);
    float4 s = *reinterpret_cast<const float4*>(&g_skip[node * 128 + lane * 4]);
    float dn = g_den[node];
    float inv = dn > 0.f ? 1.f / dn : 0.f;

    float v0 = fmaf(a.x, inv, s.x);
    float v1 = fmaf(a.y, inv, s.y);
    float v2 = fmaf(a.z, inv, s.z);
    float v3 = fmaf(a.w, inv, s.w);

    float sum = v0 + v1 + v2 + v3;
#pragma unroll
    for (int off = 16; off; off >>= 1) sum += __shfl_xor_sync(0xffffffffu, sum, off);
    float mu = sum * (1.f / 128.f);

    float d0 = v0 - mu, d1 = v1 - mu, d2 = v2 - mu, d3 = v3 - mu;
    float sq = d0 * d0 + d1 * d1 + d2 * d2 + d3 * d3;
#pragma unroll
    for (int off = 16; off; off >>= 1) sq += __shfl_xor_sync(0xffffffffu, sq, off);
    float rs = rsqrtf(sq * (1.f / 128.f) + 1e-5f);

    float4 gm = *reinterpret_cast<const float4*>(&gamma[lane * 4]);
    float4 bt = *reinterpret_cast<const float4*>(&beta[lane * 4]);
    float4 o;
    o.x = fmaf(d0 * rs, gm.x, bt.x);
    o.y = fmaf(d1 * rs, gm.y, bt.y);
    o.z = fmaf(d2 * rs, gm.z, bt.z);
    o.w = fmaf(d3 * rs, gm.w, bt.w);
    *reinterpret_cast<float4*>(&out[node * 128 + lane * 4]) = o;
}

extern "C" void kernel_launch(void* const* d_in, const int* in_sizes, int n_in,
                              void* d_out, int out_size)
{
    const float* x      = (const float*)d_in[0];
    const int*   ei     = (const int*)d_in[1];
    const float* W_src  = (const float*)d_in[2];
    const float* b_src  = (const float*)d_in[3];
    const float* W_tgt  = (const float*)d_in[4];
    const float* W_skip = (const float*)d_in[5];
    const float* a0     = (const float*)d_in[6];
    const float* W1     = (const float*)d_in[7];
    const float* b1     = (const float*)d_in[8];
    const float* a1     = (const float*)d_in[9];
    const float* W2     = (const float*)d_in[10];
    const float* b2     = (const float*)d_in[11];
    const float* Wg     = (const float*)d_in[12];
    const float* gamma  = (const float*)d_in[13];
    const float* beta   = (const float*)d_in[14];
    float* out = (float*)d_out;

    int N = in_sizes[0] / 128;
    int E = in_sizes[1] / 2;
    if (E > EMAX) E = EMAX;

    static int sms = 0;
    if (sms == 0) {
        cudaFuncSetAttribute(node3_kernel, cudaFuncAttributeMaxDynamicSharedMemorySize, NODE_SMEM_BYTES);
        cudaFuncSetAttribute(edge_kernel, cudaFuncAttributeMaxDynamicSharedMemorySize, EDGE_SMEM_BYTES);
        int dev = 0, v = 148;
        cudaGetDevice(&dev);
        cudaDeviceGetAttribute(&v, cudaDevAttrMultiProcessorCount, dev);
        sms = (v > 0) ? v : 148;
    }

    zero_kernel<<<256, 256>>>(N);
    hist_kernel<<<(E + 255) / 256, 256>>>(ei, E, N);
    scan_kernel<<<1, 1024>>>(N);
    scatter_kernel<<<(E + 255) / 256, 256>>>(ei, E, N);
    int nb = (N + 63) / 64;
    node3_kernel<<<nb, 256, NODE_SMEM_BYTES>>>(x, W_src, b_src, W_tgt, W_skip, N);
    edge_kernel<<<sms * 2, 256, EDGE_SMEM_BYTES>>>(W1, b1, W2, b2, Wg, a0, a1, E, N);
    final_kernel<<<(N * 32 + 255) / 256, 256>>>(gamma, beta, out, N);
}